// round 2
// baseline (speedup 1.0000x reference)
#include <cuda_runtime.h>
#include <math.h>
#include <stdint.h>

#define NRTOK 16384
#define NTOK  32768      // B*Nr
#define MM    64
#define AD    128
#define HIDN  512
#define SCALE 0.17677669529663687f  // 1/sqrt(32)

// scratch: x = post-LN1 (residual base for final add), y = post-LN2 (MLP input)
__device__ float g_x[NTOK * AD];
__device__ float g_y[NTOK * AD];

// ===========================================================================
// Kernel 1: per-token masked multi-head attention + residual + LN1 + LN2
// grid = 32768 blocks (1 token each), 256 threads
// ===========================================================================
__global__ __launch_bounds__(256)
void bev_attn_kernel(const float* __restrict__ Q, const float* __restrict__ K,
                     const float* __restrict__ V, const int* __restrict__ mask,
                     const float* __restrict__ ln1g, const float* __restrict__ ln1b,
                     const float* __restrict__ ln2g, const float* __restrict__ ln2b)
{
    __shared__ float Ls[256];   // logits [h][m]
    __shared__ float As[256];   // probs  [h][m]
    __shared__ float Ps[256];   // V partials
    __shared__ float Ms[MM];    // mask addend
    __shared__ float2 Rs[4], Rs2[4];

    const int tid  = threadIdx.x;
    const int lane = tid & 31;
    const int wid  = tid >> 5;
    const size_t t = blockIdx.x;

    // phase-A roles: warp w -> head h=w&3, m-range base mb=(w>>2)*32, lane = d
    const int hh = wid & 3;
    const int mb = (wid >> 2) << 5;
    const int a  = (hh << 5) + lane;

    if (tid < MM)
        Ms[tid] = mask[((t & (NRTOK - 1)) << 6) + tid] ? -1e30f : 0.0f;

    const float q = Q[t * AD + a];

    // ---- logits: p[i] = q_d * K[mb+i][a], coalesced 128B warp loads ----
    const float* Kp = K + (t * MM + mb) * AD + a;
    float p[32];
#pragma unroll
    for (int i = 0; i < 32; i++) p[i] = q * Kp[(size_t)i * AD];

    // butterfly transpose-reduce: lane l ends with full d-sum for m = mb + l
#pragma unroll
    for (int s = 16; s >= 1; s >>= 1) {
        const bool hi = (lane & s) != 0;
#pragma unroll
        for (int i = 0; i < 16; i++) {
            if (i < s) {
                float send = hi ? p[i] : p[i + s];
                float recv = __shfl_xor_sync(0xffffffffu, send, s);
                p[i] = (hi ? p[i + s] : p[i]) + recv;
            }
        }
    }
    __syncthreads();                                   // Ms ready, Ls free
    Ls[(hh << 6) + mb + lane] = p[0] * SCALE + Ms[mb + lane];
    __syncthreads();

    // ---- softmax: warp w<4 handles head w over 64 m ----
    if (wid < 4) {
        float l0 = Ls[(wid << 6) + lane];
        float l1 = Ls[(wid << 6) + 32 + lane];
        float mx = fmaxf(l0, l1);
#pragma unroll
        for (int s = 16; s >= 1; s >>= 1)
            mx = fmaxf(mx, __shfl_xor_sync(0xffffffffu, mx, s));
        float e0 = __expf(l0 - mx), e1 = __expf(l1 - mx);
        float ss = e0 + e1;
#pragma unroll
        for (int s = 16; s >= 1; s >>= 1)
            ss += __shfl_xor_sync(0xffffffffu, ss, s);
        float inv = 1.0f / ss;
        As[(wid << 6) + lane]      = e0 * inv;
        As[(wid << 6) + 32 + lane] = e1 * inv;
    }
    __syncthreads();

    // ---- out[a] = sum_m attn[h][m] * V[m][a], coalesced V stream ----
    {
        const int aV = tid & 127;
        const int gV = tid >> 7;          // m-half
        const int hA = aV >> 5;
        const float* Vp = V + (t * MM + ((size_t)gV << 5)) * AD + aV;
        float acc = 0.0f;
#pragma unroll
        for (int i = 0; i < 32; i++)
            acc += As[(hA << 6) + (gV << 5) + i] * Vp[(size_t)i * AD];
        Ps[tid] = acc;
    }
    __syncthreads();

    // ---- residual + LN1 + LN2 (threads 0..127, a = tid) ----
    float x = 0.0f, xn = 0.0f;
    if (tid < AD) {
        x = q + Ps[tid] + Ps[tid + 128];
        float sx = x, sxx = x * x;
#pragma unroll
        for (int s = 16; s >= 1; s >>= 1) {
            sx  += __shfl_xor_sync(0xffffffffu, sx,  s);
            sxx += __shfl_xor_sync(0xffffffffu, sxx, s);
        }
        if (lane == 0) Rs[wid] = make_float2(sx, sxx);
    }
    __syncthreads();
    if (tid < AD) {
        float tsum = Rs[0].x + Rs[1].x + Rs[2].x + Rs[3].x;
        float tsq  = Rs[0].y + Rs[1].y + Rs[2].y + Rs[3].y;
        float mu   = tsum * (1.0f / AD);
        float var  = tsq * (1.0f / AD) - mu * mu;
        float rstd = rsqrtf(var + 1e-5f);
        xn = (x - mu) * rstd * ln1g[tid] + ln1b[tid];
        float sx = xn, sxx = xn * xn;
#pragma unroll
        for (int s = 16; s >= 1; s >>= 1) {
            sx  += __shfl_xor_sync(0xffffffffu, sx,  s);
            sxx += __shfl_xor_sync(0xffffffffu, sxx, s);
        }
        if (lane == 0) Rs2[wid] = make_float2(sx, sxx);
    }
    __syncthreads();
    if (tid < AD) {
        float tsum = Rs2[0].x + Rs2[1].x + Rs2[2].x + Rs2[3].x;
        float tsq  = Rs2[0].y + Rs2[1].y + Rs2[2].y + Rs2[3].y;
        float mu2   = tsum * (1.0f / AD);
        float var2  = tsq * (1.0f / AD) - mu2 * mu2;
        float rstd2 = rsqrtf(var2 + 1e-5f);
        float y = (xn - mu2) * rstd2 * ln2g[tid] + ln2b[tid];
        g_x[t * AD + tid] = xn;
        g_y[t * AD + tid] = y;
    }
}

// ===========================================================================
// Kernel 2: MLP  out = x + gelu(y @ W1 + b1) @ W2 + b2
// grid = 512 blocks (64 tokens each), 256 threads, hidden in chunks of 64
// ===========================================================================
#define TT   64                 // tokens per block
#define HC   64                 // hidden chunk
#define YS_STRIDE  132
#define W1_STRIDE  68
#define W2_STRIDE  132
#define HS_STRIDE  68

struct MlpSmem {
    float Ys[TT * YS_STRIDE];    // y tile [t][k]
    float W1s[AD * W1_STRIDE];   // W1 chunk [k][jj]
    float W2s[HC * W2_STRIDE];   // W2 chunk [jj][a]
    float Hs[TT * HS_STRIDE];    // gelu hidden chunk [t][jj]
};
#define MLP_SMEM_BYTES ((int)sizeof(MlpSmem))

__global__ __launch_bounds__(256)
void bev_mlp_kernel(const float* __restrict__ W1, const float* __restrict__ b1,
                    const float* __restrict__ W2, const float* __restrict__ b2,
                    float* __restrict__ Out)
{
    extern __shared__ char smem_raw[];
    MlpSmem& sm = *reinterpret_cast<MlpSmem*>(smem_raw);
    const int tid = threadIdx.x;
    const size_t T0 = (size_t)blockIdx.x * TT;

    // stage y tile: coalesced float4
#pragma unroll
    for (int i = 0; i < 8; i++) {
        int e = tid + 256 * i;           // 2048 float4
        int tt = e >> 5, q4 = (e & 31) << 2;
        float4 v = *reinterpret_cast<const float4*>(&g_y[(T0 + tt) * AD + q4]);
        *reinterpret_cast<float4*>(&sm.Ys[tt * YS_STRIDE + q4]) = v;
    }

    // GEMM1 tile: 4 tokens x 4 hidden ; GEMM2 tile: 4 tokens x 8 outputs
    const int jg = tid & 15;    const int j0 = jg << 2;
    const int tg = tid >> 4;    const int t0 = tg << 2;
    const int ag = tid & 15;    const int a0 = ag << 3;

    float acc2[32];
#pragma unroll
    for (int i = 0; i < 32; i++) acc2[i] = 0.0f;

    for (int c = 0; c < HIDN / HC; c++) {
        // stage W1 chunk [128][64] and W2 chunk [64][128], coalesced
        const float* W1c = W1 + c * HC;
        const float* W2c = W2 + (size_t)(c * HC) * AD;
#pragma unroll
        for (int i = 0; i < 32; i++) {
            int e = tid + 256 * i;       // 8192
            int k = e >> 6, jj = e & 63;
            sm.W1s[k * W1_STRIDE + jj] = W1c[(size_t)k * HIDN + jj];
        }
#pragma unroll
        for (int i = 0; i < 32; i++) {
            int e = tid + 256 * i;       // 8192
            int jj = e >> 7, aa = e & 127;
            sm.W2s[jj * W2_STRIDE + aa] = W2c[(size_t)jj * AD + aa];
        }
        __syncthreads();

        // ---- GEMM1: H[t0..t0+3][j0..j0+3] = Ys @ W1chunk ----
        float acc1[16];
#pragma unroll
        for (int i = 0; i < 16; i++) acc1[i] = 0.0f;
#pragma unroll 4
        for (int k = 0; k < AD; k++) {
            float4 w = *reinterpret_cast<const float4*>(&sm.W1s[k * W1_STRIDE + j0]);
            float y0 = sm.Ys[(t0 + 0) * YS_STRIDE + k];
            float y1 = sm.Ys[(t0 + 1) * YS_STRIDE + k];
            float y2 = sm.Ys[(t0 + 2) * YS_STRIDE + k];
            float y3 = sm.Ys[(t0 + 3) * YS_STRIDE + k];
            acc1[0]  += y0 * w.x; acc1[1]  += y0 * w.y; acc1[2]  += y0 * w.z; acc1[3]  += y0 * w.w;
            acc1[4]  += y1 * w.x; acc1[5]  += y1 * w.y; acc1[6]  += y1 * w.z; acc1[7]  += y1 * w.w;
            acc1[8]  += y2 * w.x; acc1[9]  += y2 * w.y; acc1[10] += y2 * w.z; acc1[11] += y2 * w.w;
            acc1[12] += y3 * w.x; acc1[13] += y3 * w.y; acc1[14] += y3 * w.z; acc1[15] += y3 * w.w;
        }
        // exact gelu + bias -> Hs
#pragma unroll
        for (int ttl = 0; ttl < 4; ttl++) {
#pragma unroll
            for (int jj = 0; jj < 4; jj++) {
                float h = acc1[ttl * 4 + jj] + __ldg(&b1[c * HC + j0 + jj]);
                float g = 0.5f * h * (1.0f + erff(h * 0.70710678118654752f));
                sm.Hs[(t0 + ttl) * HS_STRIDE + j0 + jj] = g;
            }
        }
        __syncthreads();

        // ---- GEMM2: acc2[t0..+3][a0..+7] += Hchunk @ W2chunk ----
#pragma unroll 4
        for (int j = 0; j < HC; j++) {
            float4 wA = *reinterpret_cast<const float4*>(&sm.W2s[j * W2_STRIDE + a0]);
            float4 wB = *reinterpret_cast<const float4*>(&sm.W2s[j * W2_STRIDE + a0 + 4]);
            float g0 = sm.Hs[(t0 + 0) * HS_STRIDE + j];
            float g1 = sm.Hs[(t0 + 1) * HS_STRIDE + j];
            float g2 = sm.Hs[(t0 + 2) * HS_STRIDE + j];
            float g3 = sm.Hs[(t0 + 3) * HS_STRIDE + j];
            acc2[0]  += g0 * wA.x; acc2[1]  += g0 * wA.y; acc2[2]  += g0 * wA.z; acc2[3]  += g0 * wA.w;
            acc2[4]  += g0 * wB.x; acc2[5]  += g0 * wB.y; acc2[6]  += g0 * wB.z; acc2[7]  += g0 * wB.w;
            acc2[8]  += g1 * wA.x; acc2[9]  += g1 * wA.y; acc2[10] += g1 * wA.z; acc2[11] += g1 * wA.w;
            acc2[12] += g1 * wB.x; acc2[13] += g1 * wB.y; acc2[14] += g1 * wB.z; acc2[15] += g1 * wB.w;
            acc2[16] += g2 * wA.x; acc2[17] += g2 * wA.y; acc2[18] += g2 * wA.z; acc2[19] += g2 * wA.w;
            acc2[20] += g2 * wB.x; acc2[21] += g2 * wB.y; acc2[22] += g2 * wB.z; acc2[23] += g2 * wB.w;
            acc2[24] += g3 * wA.x; acc2[25] += g3 * wA.y; acc2[26] += g3 * wA.z; acc2[27] += g3 * wA.w;
            acc2[28] += g3 * wB.x; acc2[29] += g3 * wB.y; acc2[30] += g3 * wB.z; acc2[31] += g3 * wB.w;
        }
        __syncthreads();   // before restaging W1s/W2s/Hs
    }

    // ---- epilogue: out = x + acc2 + b2 (float4 stores) ----
#pragma unroll
    for (int ttl = 0; ttl < 4; ttl++) {
        size_t row = (T0 + t0 + ttl) * AD;
#pragma unroll
        for (int half = 0; half < 2; half++) {
            int ab = a0 + half * 4;
            float4 xv = *reinterpret_cast<const float4*>(&g_x[row + ab]);
            float4 o;
            o.x = xv.x + acc2[ttl * 8 + half * 4 + 0] + __ldg(&b2[ab + 0]);
            o.y = xv.y + acc2[ttl * 8 + half * 4 + 1] + __ldg(&b2[ab + 1]);
            o.z = xv.z + acc2[ttl * 8 + half * 4 + 2] + __ldg(&b2[ab + 2]);
            o.w = xv.w + acc2[ttl * 8 + half * 4 + 3] + __ldg(&b2[ab + 3]);
            *reinterpret_cast<float4*>(&Out[row + ab]) = o;
        }
    }
}

// ===========================================================================
extern "C" void kernel_launch(void* const* d_in, const int* in_sizes, int n_in,
                              void* d_out, int out_size)
{
    const float* Q    = (const float*)d_in[0];
    const float* K    = (const float*)d_in[1];
    const float* V    = (const float*)d_in[2];
    const int*   mask = (const int*)  d_in[3];
    const float* ln1g = (const float*)d_in[4];
    const float* ln1b = (const float*)d_in[5];
    const float* ln2g = (const float*)d_in[6];
    const float* ln2b = (const float*)d_in[7];
    const float* W1   = (const float*)d_in[8];
    const float* b1   = (const float*)d_in[9];
    const float* W2   = (const float*)d_in[10];
    const float* b2   = (const float*)d_in[11];
    float* Out = (float*)d_out;

    static bool attr_set = false;
    if (!attr_set) {
        cudaFuncSetAttribute(bev_mlp_kernel,
                             cudaFuncAttributeMaxDynamicSharedMemorySize,
                             MLP_SMEM_BYTES);
        attr_set = true;
    }

    bev_attn_kernel<<<NTOK, 256>>>(Q, K, V, mask, ln1g, ln1b, ln2g, ln2b);
    bev_mlp_kernel<<<NTOK / TT, 256, MLP_SMEM_BYTES>>>(W1, b1, W2, b2, Out);
}

// round 4
// speedup vs baseline: 1.0519x; 1.0519x over previous
#include <cuda_runtime.h>
#include <math.h>
#include <stdint.h>

#define NRTOK 16384
#define NTOK  32768      // B*Nr
#define MM    64
#define AD    128
#define HIDN  512
#define TT    64         // tokens per CTA tile
#define HC    64         // hidden chunk
#define SCALE 0.17677669529663687f  // 1/sqrt(32)

#define YT_STR 68        // YsT row stride (floats)
#define W1_STR 68        // W1 chunk row stride
#define W2_STR 132       // W2 chunk row stride
#define HT_STR 68        // HsT row stride

// scratch: x = post-LN1 (residual base for final add)
__device__ float g_x[NTOK * AD];

struct SmemF {
    float YsT[AD * YT_STR];      // y^T: [k][t], written during attention phase
    float W[AD * W1_STR];        // W1 chunk [k][j] (stride 68)  OR  W2 chunk [j][a] (stride 132)
    union {
        float HsT[HC * HT_STR];  // gelu(h)^T: [j][t]
        struct {
            float Ls[256], As[256], Ps[256], Ms[MM];
            float2 Rs[4], Rs2[4];
        } at;
    } u;
};
#define SMEM_BYTES ((int)sizeof(SmemF))

__global__ __launch_bounds__(256, 2)
void bev_fused_kernel(const float* __restrict__ Q, const float* __restrict__ K,
                      const float* __restrict__ V, const int* __restrict__ mask,
                      const float* __restrict__ ln1g, const float* __restrict__ ln1b,
                      const float* __restrict__ ln2g, const float* __restrict__ ln2b,
                      const float* __restrict__ W1, const float* __restrict__ b1,
                      const float* __restrict__ W2, const float* __restrict__ b2,
                      float* __restrict__ Out)
{
    extern __shared__ char smem_raw[];
    SmemF& sm = *reinterpret_cast<SmemF*>(smem_raw);

    const int tid  = threadIdx.x;
    const int lane = tid & 31;
    const int wid  = tid >> 5;
    const size_t T0 = (size_t)blockIdx.x * TT;

    // attention roles: warp w -> head h=w&3, m-base mb=(w>>2)*32, lane = d
    const int hh = wid & 3;
    const int mb = (wid >> 2) << 5;
    const int a  = (hh << 5) + lane;

    // per-thread LN params (a == tid for tid<128)
    float l1gv = 0.f, l1bv = 0.f, l2gv = 0.f, l2bv = 0.f;
    if (tid < AD) {
        l1gv = ln1g[tid]; l1bv = ln1b[tid];
        l2gv = ln2g[tid]; l2bv = ln2b[tid];
    }

    // =========================== phase 1: attention + LN1 + LN2 ===========================
    for (int tl = 0; tl < TT; tl++) {
        const size_t t = T0 + tl;

        if (tid < MM)
            sm.u.at.Ms[tid] = mask[((t & (NRTOK - 1)) << 6) + tid] ? -1e30f : 0.0f;

        const float q = Q[t * AD + a];

        // logits: p[i] = q_d * K[mb+i][a], coalesced 128B warp loads
        const float* Kp = K + (t * MM + mb) * AD + a;
        float p[32];
#pragma unroll
        for (int i = 0; i < 32; i++) p[i] = q * Kp[(size_t)i * AD];

        // butterfly transpose-reduce: lane l ends with full d-sum for m = mb + l
#pragma unroll
        for (int s = 16; s >= 1; s >>= 1) {
            const bool hi = (lane & s) != 0;
#pragma unroll
            for (int i = 0; i < 16; i++) {
                if (i < s) {
                    float send = hi ? p[i] : p[i + s];
                    float recv = __shfl_xor_sync(0xffffffffu, send, s);
                    p[i] = (hi ? p[i + s] : p[i]) + recv;
                }
            }
        }
        __syncthreads();                                   // S1: Ms ready, Ls free
        sm.u.at.Ls[(hh << 6) + mb + lane] = p[0] * SCALE + sm.u.at.Ms[mb + lane];
        __syncthreads();                                   // S2

        // softmax: warp w<4 handles head w over 64 m
        if (wid < 4) {
            float l0 = sm.u.at.Ls[(wid << 6) + lane];
            float l1 = sm.u.at.Ls[(wid << 6) + 32 + lane];
            float mx = fmaxf(l0, l1);
#pragma unroll
            for (int s = 16; s >= 1; s >>= 1)
                mx = fmaxf(mx, __shfl_xor_sync(0xffffffffu, mx, s));
            float e0 = __expf(l0 - mx), e1 = __expf(l1 - mx);
            float ss = e0 + e1;
#pragma unroll
            for (int s = 16; s >= 1; s >>= 1)
                ss += __shfl_xor_sync(0xffffffffu, ss, s);
            float inv = 1.0f / ss;
            sm.u.at.As[(wid << 6) + lane]      = e0 * inv;
            sm.u.at.As[(wid << 6) + 32 + lane] = e1 * inv;
        }
        __syncthreads();                                   // S3

        // out[a] = sum_m attn[h][m] * V[m][a], coalesced V stream
        {
            const int aV = tid & 127;
            const int gV = tid >> 7;
            const int hA = aV >> 5;
            const float* Vp = V + (t * MM + ((size_t)gV << 5)) * AD + aV;
            float acc = 0.0f;
#pragma unroll
            for (int i = 0; i < 32; i++)
                acc += sm.u.at.As[(hA << 6) + (gV << 5) + i] * Vp[(size_t)i * AD];
            sm.u.at.Ps[tid] = acc;
        }
        __syncthreads();                                   // S4

        float x = 0.0f, xn = 0.0f;
        if (tid < AD) {
            x = q + sm.u.at.Ps[tid] + sm.u.at.Ps[tid + 128];
            float sx = x, sxx = x * x;
#pragma unroll
            for (int s = 16; s >= 1; s >>= 1) {
                sx  += __shfl_xor_sync(0xffffffffu, sx,  s);
                sxx += __shfl_xor_sync(0xffffffffu, sxx, s);
            }
            if (lane == 0) sm.u.at.Rs[wid] = make_float2(sx, sxx);
        }
        __syncthreads();                                   // S5
        if (tid < AD) {
            float tsum = sm.u.at.Rs[0].x + sm.u.at.Rs[1].x + sm.u.at.Rs[2].x + sm.u.at.Rs[3].x;
            float tsq  = sm.u.at.Rs[0].y + sm.u.at.Rs[1].y + sm.u.at.Rs[2].y + sm.u.at.Rs[3].y;
            float mu   = tsum * (1.0f / AD);
            float var  = tsq * (1.0f / AD) - mu * mu;
            float rstd = rsqrtf(var + 1e-5f);
            xn = (x - mu) * rstd * l1gv + l1bv;
            float sx = xn, sxx = xn * xn;
#pragma unroll
            for (int s = 16; s >= 1; s >>= 1) {
                sx  += __shfl_xor_sync(0xffffffffu, sx,  s);
                sxx += __shfl_xor_sync(0xffffffffu, sxx, s);
            }
            if (lane == 0) sm.u.at.Rs2[wid] = make_float2(sx, sxx);
        }
        __syncthreads();                                   // S6
        if (tid < AD) {
            float tsum = sm.u.at.Rs2[0].x + sm.u.at.Rs2[1].x + sm.u.at.Rs2[2].x + sm.u.at.Rs2[3].x;
            float tsq  = sm.u.at.Rs2[0].y + sm.u.at.Rs2[1].y + sm.u.at.Rs2[2].y + sm.u.at.Rs2[3].y;
            float mu2   = tsum * (1.0f / AD);
            float var2  = tsq * (1.0f / AD) - mu2 * mu2;
            float rstd2 = rsqrtf(var2 + 1e-5f);
            float y = (xn - mu2) * rstd2 * l2gv + l2bv;
            g_x[t * AD + tid] = xn;
            sm.YsT[tid * YT_STR + tl] = y;
        }
        // next-iter hazards are separated by >=1 sync: no extra barrier needed here
    }

    // =========================== phase 2: MLP on the tile ===========================
    const int tg = tid >> 4;         // 16 token-groups
    const int jg = tid & 15;         // 16 col-groups
    const int t0 = tg << 2;          // tokens t0..t0+3
    const int j0 = jg << 2;          // GEMM1 hid cols j0..j0+3 ; GEMM2 out cols j0..j0+3 and j0+64..j0+67

    float acc2[32];
#pragma unroll
    for (int i = 0; i < 32; i++) acc2[i] = 0.0f;

    for (int c = 0; c < HIDN / HC; c++) {
        __syncthreads();   // covers: attention->MLP transition, and W/HsT reuse across chunks

        // ---- stage W1 chunk [128 k][64 j] (float4, coalesced) ----
        const float* W1c = W1 + c * HC;
#pragma unroll
        for (int i = 0; i < 8; i++) {
            int e  = tid + 256 * i;              // 2048 float4
            int k  = e >> 4;
            int j4 = (e & 15) << 2;
            float4 v = *reinterpret_cast<const float4*>(&W1c[(size_t)k * HIDN + j4]);
            *reinterpret_cast<float4*>(&sm.W[k * W1_STR + j4]) = v;
        }
        __syncthreads();

        // ---- GEMM1: acc1[4 tok][4 hid] = YsT^T @ W1chunk ----
        float acc1[16];
#pragma unroll
        for (int i = 0; i < 16; i++) acc1[i] = 0.0f;
#pragma unroll 4
        for (int k = 0; k < AD; k++) {
            float4 y4 = *reinterpret_cast<const float4*>(&sm.YsT[k * YT_STR + t0]);
            float4 w4 = *reinterpret_cast<const float4*>(&sm.W[k * W1_STR + j0]);
            acc1[0]  += y4.x * w4.x; acc1[1]  += y4.x * w4.y; acc1[2]  += y4.x * w4.z; acc1[3]  += y4.x * w4.w;
            acc1[4]  += y4.y * w4.x; acc1[5]  += y4.y * w4.y; acc1[6]  += y4.y * w4.z; acc1[7]  += y4.y * w4.w;
            acc1[8]  += y4.z * w4.x; acc1[9]  += y4.z * w4.y; acc1[10] += y4.z * w4.z; acc1[11] += y4.z * w4.w;
            acc1[12] += y4.w * w4.x; acc1[13] += y4.w * w4.y; acc1[14] += y4.w * w4.z; acc1[15] += y4.w * w4.w;
        }

        // ---- bias + exact gelu -> HsT (float4 across tokens) ----
#pragma unroll
        for (int jj = 0; jj < 4; jj++) {
            float bj = __ldg(&b1[c * HC + j0 + jj]);
            float h0 = acc1[0 * 4 + jj] + bj;
            float h1 = acc1[1 * 4 + jj] + bj;
            float h2 = acc1[2 * 4 + jj] + bj;
            float h3 = acc1[3 * 4 + jj] + bj;
            float4 g;
            g.x = 0.5f * h0 * (1.0f + erff(h0 * 0.70710678118654752f));
            g.y = 0.5f * h1 * (1.0f + erff(h1 * 0.70710678118654752f));
            g.z = 0.5f * h2 * (1.0f + erff(h2 * 0.70710678118654752f));
            g.w = 0.5f * h3 * (1.0f + erff(h3 * 0.70710678118654752f));
            *reinterpret_cast<float4*>(&sm.u.HsT[(j0 + jj) * HT_STR + t0]) = g;
        }
        __syncthreads();

        // ---- stage W2 chunk [64 j][128 a] (float4, coalesced) ----
        const float* W2c = W2 + (size_t)(c * HC) * AD;
#pragma unroll
        for (int i = 0; i < 8; i++) {
            int e  = tid + 256 * i;              // 2048 float4
            int j  = e >> 5;
            int a4 = (e & 31) << 2;
            float4 v = *reinterpret_cast<const float4*>(&W2c[(size_t)j * AD + a4]);
            *reinterpret_cast<float4*>(&sm.W[j * W2_STR + a4]) = v;
        }
        __syncthreads();

        // ---- GEMM2: acc2[4 tok][cols j0..j0+3, j0+64..j0+67] += Hchunk @ W2chunk ----
#pragma unroll 4
        for (int j = 0; j < HC; j++) {
            float4 g4 = *reinterpret_cast<const float4*>(&sm.u.HsT[j * HT_STR + t0]);
            float4 wA = *reinterpret_cast<const float4*>(&sm.W[j * W2_STR + j0]);
            float4 wB = *reinterpret_cast<const float4*>(&sm.W[j * W2_STR + j0 + 64]);
            acc2[0]  += g4.x * wA.x; acc2[1]  += g4.x * wA.y; acc2[2]  += g4.x * wA.z; acc2[3]  += g4.x * wA.w;
            acc2[4]  += g4.x * wB.x; acc2[5]  += g4.x * wB.y; acc2[6]  += g4.x * wB.z; acc2[7]  += g4.x * wB.w;
            acc2[8]  += g4.y * wA.x; acc2[9]  += g4.y * wA.y; acc2[10] += g4.y * wA.z; acc2[11] += g4.y * wA.w;
            acc2[12] += g4.y * wB.x; acc2[13] += g4.y * wB.y; acc2[14] += g4.y * wB.z; acc2[15] += g4.y * wB.w;
            acc2[16] += g4.z * wA.x; acc2[17] += g4.z * wA.y; acc2[18] += g4.z * wA.z; acc2[19] += g4.z * wA.w;
            acc2[20] += g4.z * wB.x; acc2[21] += g4.z * wB.y; acc2[22] += g4.z * wB.z; acc2[23] += g4.z * wB.w;
            acc2[24] += g4.w * wA.x; acc2[25] += g4.w * wA.y; acc2[26] += g4.w * wA.z; acc2[27] += g4.w * wA.w;
            acc2[28] += g4.w * wB.x; acc2[29] += g4.w * wB.y; acc2[30] += g4.w * wB.z; acc2[31] += g4.w * wB.w;
        }
    }

    // ---- epilogue: out = x + acc2 + b2 (float4) ----
#pragma unroll
    for (int tt2 = 0; tt2 < 4; tt2++) {
        size_t row = (T0 + t0 + tt2) * (size_t)AD;
        {
            float4 xv = *reinterpret_cast<const float4*>(&g_x[row + j0]);
            float4 o;
            o.x = xv.x + acc2[tt2 * 8 + 0] + __ldg(&b2[j0 + 0]);
            o.y = xv.y + acc2[tt2 * 8 + 1] + __ldg(&b2[j0 + 1]);
            o.z = xv.z + acc2[tt2 * 8 + 2] + __ldg(&b2[j0 + 2]);
            o.w = xv.w + acc2[tt2 * 8 + 3] + __ldg(&b2[j0 + 3]);
            *reinterpret_cast<float4*>(&Out[row + j0]) = o;
        }
        {
            float4 xv = *reinterpret_cast<const float4*>(&g_x[row + j0 + 64]);
            float4 o;
            o.x = xv.x + acc2[tt2 * 8 + 4] + __ldg(&b2[j0 + 64]);
            o.y = xv.y + acc2[tt2 * 8 + 5] + __ldg(&b2[j0 + 65]);
            o.z = xv.z + acc2[tt2 * 8 + 6] + __ldg(&b2[j0 + 66]);
            o.w = xv.w + acc2[tt2 * 8 + 7] + __ldg(&b2[j0 + 67]);
            *reinterpret_cast<float4*>(&Out[row + j0 + 64]) = o;
        }
    }
}

// ===========================================================================
extern "C" void kernel_launch(void* const* d_in, const int* in_sizes, int n_in,
                              void* d_out, int out_size)
{
    const float* Q    = (const float*)d_in[0];
    const float* K    = (const float*)d_in[1];
    const float* V    = (const float*)d_in[2];
    const int*   mask = (const int*)  d_in[3];
    const float* ln1g = (const float*)d_in[4];
    const float* ln1b = (const float*)d_in[5];
    const float* ln2g = (const float*)d_in[6];
    const float* ln2b = (const float*)d_in[7];
    const float* W1   = (const float*)d_in[8];
    const float* b1   = (const float*)d_in[9];
    const float* W2   = (const float*)d_in[10];
    const float* b2   = (const float*)d_in[11];
    float* Out = (float*)d_out;

    static bool attr_set = false;
    if (!attr_set) {
        cudaFuncSetAttribute(bev_fused_kernel,
                             cudaFuncAttributeMaxDynamicSharedMemorySize,
                             SMEM_BYTES);
        attr_set = true;
    }

    bev_fused_kernel<<<NTOK / TT, 256, SMEM_BYTES>>>(
        Q, K, V, mask, ln1g, ln1b, ln2g, ln2b, W1, b1, W2, b2, Out);
}